// round 8
// baseline (speedup 1.0000x reference)
#include <cuda_runtime.h>
#include <cuda_bf16.h>
#include <cstddef>

// Problem constants
#define QL 1024            // qlen == klen == rlen
#define BSZ 4
#define DM 1024            // d_model
#define NH 16
#define DH 64
#define ROWS (QL * BSZ)    // 4096 token rows
#define QKVC (3 * NH * DH) // 3072

// ---------------- scratch (static device globals; no dynamic alloc) -------------
__device__ float g_qkv[ROWS * QKVC];  // 48 MB  [row, 3072]  row = i*4 + b
__device__ float g_rk[QL * DM];       // 4 MB   [p, n*64+d]
__device__ float g_vec[ROWS * DM];    // 16 MB  [row, n*64+d]
__device__ float g_attn[ROWS * DM];   // 16 MB  attn_out before LN

// ---------------- packed f32x2 helpers (sm_103a FFMA2 path) ---------------------
typedef unsigned long long ull_t;

union F4U {
    float4 f;
    float s[4];
    ull_t u[2];  // u[0] = {s[0], s[1]}, u[1] = {s[2], s[3]} (little-endian lanes)
};

__device__ __forceinline__ ull_t pack_dup(float x) {
    ull_t r;
    asm("mov.b64 %0, {%1, %1};" : "=l"(r) : "f"(x));
    return r;
}

__device__ __forceinline__ void ffma2(ull_t& d, ull_t a, ull_t b) {
    // d = a * b + d, lanewise fp32x2 (SASS FFMA2)
    asm("fma.rn.f32x2 %0, %1, %2, %0;" : "+l"(d) : "l"(a), "l"(b));
}

// ---------------- SGEMM core: C[M,N] = A[M,K] @ B[K,N], row-major ---------------
// BM=BN=128, BK=16, TM=TN=8, 256 threads, double-buffered smem, inner product
// via packed fma.rn.f32x2 (2 output columns per instruction). Per-element FMA
// chain identical (same k order) to the scalar version -> bit-identical results.
__device__ __forceinline__ void sgemm_tile(const float* __restrict__ A,
                                           const float* __restrict__ B,
                                           float* __restrict__ C,
                                           int N, int K, int row0, int col0) {
    __shared__ float As[2][16][128];
    __shared__ float Bs[2][16][128];
    const int tid = threadIdx.x;
    const int tx = tid & 15;   // N micro
    const int ty = tid >> 4;   // M micro

    const int aRow = tid >> 1;            // 0..127
    const int aCol = (tid & 1) * 8;       // 0 or 8 (covers 16 cols as 2 float4)
    const int bRow = tid >> 5;            // 0..7 (and bRow+8)
    const int bCol = (tid & 31) * 4;      // 0..124

    const float* aPtr = A + (size_t)(row0 + aRow) * K + aCol;
    const float* bPtr = B + (size_t)bRow * N + col0 + bCol;

    // acc2[i][j] = packed pair of output columns (tx*8 + 2j, tx*8 + 2j + 1)
    ull_t acc2[8][4];
#pragma unroll
    for (int i = 0; i < 8; i++)
#pragma unroll
        for (int j = 0; j < 4; j++) acc2[i][j] = 0ull;

    // Preload k0 = 0 into buffer 0.
    {
        float4 a0 = *(const float4*)(aPtr);
        float4 a1 = *(const float4*)(aPtr + 4);
        As[0][aCol + 0][aRow] = a0.x;
        As[0][aCol + 1][aRow] = a0.y;
        As[0][aCol + 2][aRow] = a0.z;
        As[0][aCol + 3][aRow] = a0.w;
        As[0][aCol + 4][aRow] = a1.x;
        As[0][aCol + 5][aRow] = a1.y;
        As[0][aCol + 6][aRow] = a1.z;
        As[0][aCol + 7][aRow] = a1.w;
        float4 b0 = *(const float4*)(bPtr);
        float4 b1 = *(const float4*)(bPtr + (size_t)8 * N);
        *(float4*)&Bs[0][bRow][bCol] = b0;
        *(float4*)&Bs[0][bRow + 8][bCol] = b1;
    }
    __syncthreads();

    int cur = 0;
    for (int k0 = 0; k0 < K; k0 += 16, cur ^= 1) {
        float4 a0, a1, b0, b1;
        const bool more = (k0 + 16) < K;
        if (more) {
            a0 = *(const float4*)(aPtr + k0 + 16);
            a1 = *(const float4*)(aPtr + k0 + 20);
            b0 = *(const float4*)(bPtr + (size_t)(k0 + 16) * N);
            b1 = *(const float4*)(bPtr + (size_t)(k0 + 24) * N);
        }
#pragma unroll
        for (int k = 0; k < 16; k++) {
            F4U av0, av1, bv0, bv1;
            av0.f = *(const float4*)&As[cur][k][ty * 8];
            av1.f = *(const float4*)&As[cur][k][ty * 8 + 4];
            bv0.f = *(const float4*)&Bs[cur][k][tx * 8];
            bv1.f = *(const float4*)&Bs[cur][k][tx * 8 + 4];
            ull_t br2[4] = {bv0.u[0], bv0.u[1], bv1.u[0], bv1.u[1]};
#pragma unroll
            for (int i = 0; i < 8; i++) {
                float a_s = (i < 4) ? av0.s[i] : av1.s[i - 4];
                ull_t a2 = pack_dup(a_s);
#pragma unroll
                for (int j = 0; j < 4; j++) ffma2(acc2[i][j], a2, br2[j]);
            }
        }
        if (more) {
            const int nxt = cur ^ 1;
            As[nxt][aCol + 0][aRow] = a0.x;
            As[nxt][aCol + 1][aRow] = a0.y;
            As[nxt][aCol + 2][aRow] = a0.z;
            As[nxt][aCol + 3][aRow] = a0.w;
            As[nxt][aCol + 4][aRow] = a1.x;
            As[nxt][aCol + 5][aRow] = a1.y;
            As[nxt][aCol + 6][aRow] = a1.z;
            As[nxt][aCol + 7][aRow] = a1.w;
            *(float4*)&Bs[nxt][bRow][bCol] = b0;
            *(float4*)&Bs[nxt][bRow + 8][bCol] = b1;
        }
        __syncthreads();
    }
#pragma unroll
    for (int i = 0; i < 8; i++) {
        F4U lo, hi;
        lo.u[0] = acc2[i][0];
        lo.u[1] = acc2[i][1];
        hi.u[0] = acc2[i][2];
        hi.u[1] = acc2[i][3];
        float* cRow = C + (size_t)(row0 + ty * 8 + i) * N + col0 + tx * 8;
        *(float4*)(cRow) = lo.f;
        *(float4*)(cRow + 4) = hi.f;
    }
}

// Plain single-GEMM kernel (used for vec @ W_o).
__global__ void sgemm_kernel(const float* __restrict__ A, const float* __restrict__ B,
                             float* __restrict__ C, int N, int K) {
    sgemm_tile(A, B, C, N, K, blockIdx.y * 128, blockIdx.x * 128);
}

// Fused launch: QKV GEMM (by<32) and R GEMM (by>=32, bx<8) in one grid so the
// small 64-block R GEMM fills the tail wave of the 768-block QKV GEMM instead
// of serializing after it.
__global__ void qkv_rk_kernel(const float* __restrict__ w, const float* __restrict__ Wqkv,
                              float* __restrict__ qkv,
                              const float* __restrict__ r, const float* __restrict__ Wr,
                              float* __restrict__ rk) {
    if (blockIdx.y < 32) {
        sgemm_tile(w, Wqkv, qkv, QKVC, DM, blockIdx.y * 128, blockIdx.x * 128);
    } else if (blockIdx.x < 8) {
        sgemm_tile(r, Wr, rk, DM, DM, (blockIdx.y - 32) * 128, blockIdx.x * 128);
    }
}

// ---------------- fused flash attention with relative position -------------------
// For one (i-tile of 64 rows, bn): online softmax over all causal j-tiles.
// score[i][j] = 0.125 * ((q_i + rwb)·k_j + (q_i + rrb)·rk[QL-1-(i-j)]), j <= i.
// rk term handled by 127-wide shared window: pl = 63 - il + jl.
// Output: vec[i*4+b, n*64+d] = softmax(score) @ V.
//
// Dynamic smem layout (floats):
//   sQw [64][68]  [d][il]                      4352
//   sQr [64][68]  [d][il]                      4352
//   union:
//     phase1: sK [64][68] [d][jl], sR [64][128] [d][pl]   4352 + 8192
//     phase2: sP [64][68] [il][jl], sV [64][68] [jl][d]   4352 + 4352
#define SM_QW 0
#define SM_QR (64 * 68)
#define SM_U  (2 * 64 * 68)
#define SM_K  SM_U
#define SM_R  (SM_U + 64 * 68)
#define SM_P  SM_U
#define SM_V  (SM_U + 64 * 68)
#define SM_FLOATS (2 * 64 * 68 + 64 * 68 + 64 * 128)  // 21248 floats = 85 KB

__global__ __launch_bounds__(256, 2)
void flash_kernel(const float* __restrict__ qkv, const float* __restrict__ rk,
                  const float* __restrict__ rwb, const float* __restrict__ rrb,
                  float* __restrict__ vec) {
    extern __shared__ float sm[];
    const int i0 = (15 - blockIdx.x) * 64;  // heavy tiles first
    const int bn = blockIdx.y;
    const int b = bn >> 4, n = bn & 15;
    const int tid = threadIdx.x;
    const int tx = tid & 15;   // d / jl micro (4 wide)
    const int ty = tid >> 4;   // il micro (4 wide)

    // Per-thread V-prefetch coordinates: 4 float4s cover the 64x64 V tile.
    // f = tid + k*256 ; jl = f >> 4 ; d = (f & 15) * 4
    int vjl[4], vd[4];
#pragma unroll
    for (int k = 0; k < 4; k++) {
        int f = tid + k * 256;
        vjl[k] = f >> 4;
        vd[k] = (f & 15) * 4;
    }

    // Load Q tile once: sQw/sQr [d][il]
    for (int t = tid; t < 64 * 64; t += 256) {
        int il = t >> 6, d = t & 63;
        float q = qkv[(size_t)((i0 + il) * 4 + b) * QKVC + n * 64 + d];
        sm[SM_QW + d * 68 + il] = q + rwb[n * 64 + d];
        sm[SM_QR + d * 68 + il] = q + rrb[n * 64 + d];
    }

    float acc[4][4];
    float m[4], l[4];
#pragma unroll
    for (int r = 0; r < 4; r++) {
        m[r] = -1e30f;
        l[r] = 0.f;
#pragma unroll
        for (int c = 0; c < 4; c++) acc[r][c] = 0.f;
    }

    const int ntiles = i0 / 64 + 1;
    const int pl0 = 60 - ty * 4 + tx * 4;  // min rk-window index for this thread

    for (int jt = 0; jt < ntiles; jt++) {
        const int j0 = jt * 64;

        // ---- prefetch V tile into registers (no smem touched; latency hidden
        //      under the K/sR staging + S compute below) ----
        float4 vreg[4];
#pragma unroll
        for (int k = 0; k < 4; k++) {
            vreg[k] = *(const float4*)&qkv[(size_t)((j0 + vjl[k]) * 4 + b) * QKVC +
                                           2048 + n * 64 + vd[k]];
        }

        __syncthreads();  // previous phase-2 reads of sU done (also covers Q loads)

        // ---- load K tile [d][jl] and rk window [d][pl] ----
        for (int t = tid; t < 64 * 64; t += 256) {
            int jl = t >> 6, d = t & 63;
            sm[SM_K + d * 68 + jl] =
                qkv[(size_t)((j0 + jl) * 4 + b) * QKVC + 1024 + n * 64 + d];
        }
        const int pbase = QL - 64 - i0 + j0;  // >= 0 always
        for (int t = tid; t < 64 * 128; t += 256) {
            int d = t >> 7, pl = t & 127;
            int p = pbase + pl;
            sm[SM_R + d * 128 + pl] =
                (p < QL) ? rk[(size_t)p * DM + n * 64 + d] : 0.f;  // OOB only where masked
        }
        __syncthreads();

        // ---- S = AC + BD for this thread's 4x4 patch ----
        float s[4][4];
#pragma unroll
        for (int r = 0; r < 4; r++)
#pragma unroll
            for (int c = 0; c < 4; c++) s[r][c] = 0.f;

#pragma unroll 4
        for (int d = 0; d < 64; d++) {
            float4 qw = *(const float4*)&sm[SM_QW + d * 68 + ty * 4];
            float4 qr = *(const float4*)&sm[SM_QR + d * 68 + ty * 4];
            float4 kk = *(const float4*)&sm[SM_K + d * 68 + tx * 4];
            float4 rA = *(const float4*)&sm[SM_R + d * 128 + pl0];
            float4 rB = *(const float4*)&sm[SM_R + d * 128 + pl0 + 4];
            float qwv[4] = {qw.x, qw.y, qw.z, qw.w};
            float qrv[4] = {qr.x, qr.y, qr.z, qr.w};
            float kv[4]  = {kk.x, kk.y, kk.z, kk.w};
            float rv[8]  = {rA.x, rA.y, rA.z, rA.w, rB.x, rB.y, rB.z, rB.w};
#pragma unroll
            for (int r = 0; r < 4; r++)
#pragma unroll
                for (int c = 0; c < 4; c++) {
                    s[r][c] += qwv[r] * kv[c];
                    s[r][c] += qrv[r] * rv[3 - r + c];  // pl = pl0 + 3 - r + c
                }
        }

        // ---- mask + scale ----
#pragma unroll
        for (int r = 0; r < 4; r++) {
            int i = i0 + ty * 4 + r;
#pragma unroll
            for (int c = 0; c < 4; c++) {
                int j = j0 + tx * 4 + c;
                s[r][c] = (j <= i) ? s[r][c] * 0.125f : -1e30f;
            }
        }

        // ---- online softmax update (row groups = 16 lanes sharing ty) ----
        float rowsum[4];
#pragma unroll
        for (int r = 0; r < 4; r++) {
            float mx = fmaxf(fmaxf(s[r][0], s[r][1]), fmaxf(s[r][2], s[r][3]));
#pragma unroll
            for (int o = 1; o < 16; o <<= 1)
                mx = fmaxf(mx, __shfl_xor_sync(0xffffffffu, mx, o));
            float mnew = fmaxf(m[r], mx);
            float sc = __expf(m[r] - mnew);
            m[r] = mnew;
            l[r] *= sc;
#pragma unroll
            for (int c = 0; c < 4; c++) acc[r][c] *= sc;
            float rs = 0.f;
#pragma unroll
            for (int c = 0; c < 4; c++) {
                float p = __expf(s[r][c] - mnew);
                s[r][c] = p;
                rs += p;
            }
            rowsum[r] = rs;
        }
#pragma unroll
        for (int r = 0; r < 4; r++) {
#pragma unroll
            for (int o = 1; o < 16; o <<= 1)
                rowsum[r] += __shfl_xor_sync(0xffffffffu, rowsum[r], o);
            l[r] += rowsum[r];
        }

        __syncthreads();  // done reading sK/sR

        // ---- write P [il][jl], store prefetched V [jl][d] ----
#pragma unroll
        for (int r = 0; r < 4; r++) {
            float4 pv = make_float4(s[r][0], s[r][1], s[r][2], s[r][3]);
            *(float4*)&sm[SM_P + (ty * 4 + r) * 68 + tx * 4] = pv;
        }
#pragma unroll
        for (int k = 0; k < 4; k++) {
            *(float4*)&sm[SM_V + vjl[k] * 68 + vd[k]] = vreg[k];
        }
        __syncthreads();

        // ---- acc += P @ V ----
#pragma unroll 4
        for (int jl = 0; jl < 64; jl++) {
            float pr[4];
#pragma unroll
            for (int r = 0; r < 4; r++) pr[r] = sm[SM_P + (ty * 4 + r) * 68 + jl];
            float4 vv = *(const float4*)&sm[SM_V + jl * 68 + tx * 4];
            float vvv[4] = {vv.x, vv.y, vv.z, vv.w};
#pragma unroll
            for (int r = 0; r < 4; r++)
#pragma unroll
                for (int c = 0; c < 4; c++) acc[r][c] += pr[r] * vvv[c];
        }
    }

    // ---- epilogue: normalize and write vec ----
#pragma unroll
    for (int r = 0; r < 4; r++) {
        float inv = 1.f / l[r];
        int i = i0 + ty * 4 + r;
        float4 o = make_float4(acc[r][0] * inv, acc[r][1] * inv,
                               acc[r][2] * inv, acc[r][3] * inv);
        *(float4*)&vec[(size_t)(i * 4 + b) * DM + n * 64 + tx * 4] = o;
    }
}

// ---------------- residual + LayerNorm (float4 + warp-shuffle reduction) ---------
__global__ void ln_kernel(const float* __restrict__ w, const float* __restrict__ attn,
                          const float* __restrict__ gamma, const float* __restrict__ beta,
                          float* __restrict__ out) {
    const int row = blockIdx.x;
    const int tid = threadIdx.x;  // 256 threads, 1 float4 each
    __shared__ float warp_s[8], warp_s2[8], stats[2];

    const float4 wv = *(const float4*)(w + (size_t)row * DM + tid * 4);
    const float4 av = *(const float4*)(attn + (size_t)row * DM + tid * 4);
    float4 v = make_float4(wv.x + av.x, wv.y + av.y, wv.z + av.z, wv.w + av.w);

    float s = v.x + v.y + v.z + v.w;
    float s2 = v.x * v.x + v.y * v.y + v.z * v.z + v.w * v.w;
#pragma unroll
    for (int o = 16; o > 0; o >>= 1) {
        s += __shfl_xor_sync(0xffffffffu, s, o);
        s2 += __shfl_xor_sync(0xffffffffu, s2, o);
    }
    if ((tid & 31) == 0) {
        warp_s[tid >> 5] = s;
        warp_s2[tid >> 5] = s2;
    }
    __syncthreads();
    if (tid < 32) {
        float ps = (tid < 8) ? warp_s[tid] : 0.f;
        float ps2 = (tid < 8) ? warp_s2[tid] : 0.f;
#pragma unroll
        for (int o = 4; o > 0; o >>= 1) {
            ps += __shfl_xor_sync(0xffffffffu, ps, o);
            ps2 += __shfl_xor_sync(0xffffffffu, ps2, o);
        }
        if (tid == 0) {
            float mu = ps * (1.f / DM);
            float var = ps2 * (1.f / DM) - mu * mu;
            stats[0] = mu;
            stats[1] = rsqrtf(var + 1e-5f);
        }
    }
    __syncthreads();
    const float mu = stats[0], rstd = stats[1];
    const float4 g4 = *(const float4*)(gamma + tid * 4);
    const float4 b4 = *(const float4*)(beta + tid * 4);
    float4 o4;
    o4.x = (v.x - mu) * rstd * g4.x + b4.x;
    o4.y = (v.y - mu) * rstd * g4.y + b4.y;
    o4.z = (v.z - mu) * rstd * g4.z + b4.z;
    o4.w = (v.w - mu) * rstd * g4.w + b4.w;
    *(float4*)(out + (size_t)row * DM + tid * 4) = o4;
}

// ---------------- launch ---------------------------------------------------------
extern "C" void kernel_launch(void* const* d_in, const int* in_sizes, int n_in,
                              void* d_out, int out_size) {
    const float* w    = (const float*)d_in[0];  // [1024, 4, 1024]
    const float* r    = (const float*)d_in[1];  // [1024, 1024]
    const float* rwb  = (const float*)d_in[2];  // [16, 64]
    const float* rrb  = (const float*)d_in[3];  // [16, 64]
    // d_in[4] = attn_mask (fixed causal tril) -- computed analytically
    const float* Wqkv = (const float*)d_in[5];  // [1024, 3072]
    const float* Wr   = (const float*)d_in[6];  // [1024, 1024]
    const float* Wo   = (const float*)d_in[7];  // [1024, 1024]
    const float* gam  = (const float*)d_in[8];  // [1024]
    const float* bet  = (const float*)d_in[9];  // [1024]
    float* out = (float*)d_out;

    float *qkv, *rk, *vec, *attn;
    cudaGetSymbolAddress((void**)&qkv, g_qkv);
    cudaGetSymbolAddress((void**)&rk, g_rk);
    cudaGetSymbolAddress((void**)&vec, g_vec);
    cudaGetSymbolAddress((void**)&attn, g_attn);

    // Unconditional (no static guard — harness rule). Idempotent host API,
    // not stream-ordered, safe under graph capture.
    cudaFuncSetAttribute(flash_kernel, cudaFuncAttributeMaxDynamicSharedMemorySize,
                         SM_FLOATS * sizeof(float));

    // 1+2) heads = w @ W_qkv [4096,3072]  fused with  r_k = r @ W_r [1024,1024]
    qkv_rk_kernel<<<dim3(24, 40), 256>>>(w, Wqkv, qkv, r, Wr, rk);
    // 3) fused attention (scores + rel-shift + softmax + PV)
    flash_kernel<<<dim3(16, 64), 256, SM_FLOATS * sizeof(float)>>>(qkv, rk, rwb, rrb, vec);
    // 4) attn_out = vec @ W_o : [4096, 1024]
    sgemm_kernel<<<dim3(8, 32), 256>>>(vec, Wo, attn, DM, DM);
    // 5) layer_norm(w + attn_out)
    ln_kernel<<<ROWS, 256>>>(w, attn, gam, bet, out);
}

// round 10
// speedup vs baseline: 1.4677x; 1.4677x over previous
#include <cuda_runtime.h>
#include <cuda_bf16.h>
#include <cstddef>
#include <cstdint>

// Problem constants
#define QL 1024            // qlen == klen == rlen
#define BSZ 4
#define DM 1024            // d_model
#define NH 16
#define DH 64
#define ROWS (QL * BSZ)    // 4096 token rows
#define QKVC (3 * NH * DH) // 3072

// ---------------- scratch (static device globals; no dynamic alloc) -------------
__device__ float g_qkv[ROWS * QKVC];  // 48 MB  [row, 3072]  row = i*4 + b
__device__ float g_rk[QL * DM];       // 4 MB   [p, n*64+d]
__device__ float g_attn[ROWS * DM];   // 16 MB  attn_out before LN

// bf16 hi/lo split operands for tensor-core GEMMs
__device__ __nv_bfloat16 g_wh[ROWS * DM],  g_wl[ROWS * DM];    // A of QKV gemm
__device__ __nv_bfloat16 g_rh[QL * DM],    g_rl[QL * DM];      // A of R gemm
__device__ __nv_bfloat16 g_vh[ROWS * DM],  g_vl[ROWS * DM];    // A of Wo gemm (from flash)
__device__ __nv_bfloat16 g_qkt_h[QKVC * DM], g_qkt_l[QKVC * DM]; // W_qkv^T [N][K]
__device__ __nv_bfloat16 g_wrt_h[DM * DM],   g_wrt_l[DM * DM];   // W_r^T
__device__ __nv_bfloat16 g_wot_h[DM * DM],   g_wot_l[DM * DM];   // W_o^T

// ---------------- fp32 -> bf16 hi/lo split helpers -------------------------------
__device__ __forceinline__ void split_bf16(float x, __nv_bfloat16& h, __nv_bfloat16& l) {
    h = __float2bfloat16(x);
    l = __float2bfloat16(x - __bfloat162float(h));
}

// Elementwise split: in [n4*4 floats] -> hi/lo bf16.
__global__ void convert_split_kernel(const float* __restrict__ in,
                                     __nv_bfloat16* __restrict__ hi,
                                     __nv_bfloat16* __restrict__ lo, int n4) {
    int i = blockIdx.x * blockDim.x + threadIdx.x;
    if (i >= n4) return;
    float4 x = ((const float4*)in)[i];
    float xs[4] = {x.x, x.y, x.z, x.w};
    __nv_bfloat16 h[4], l[4];
#pragma unroll
    for (int j = 0; j < 4; j++) split_bf16(xs[j], h[j], l[j]);
    ((__nv_bfloat162*)hi)[i * 2]     = __halves2bfloat162(h[0], h[1]);
    ((__nv_bfloat162*)hi)[i * 2 + 1] = __halves2bfloat162(h[2], h[3]);
    ((__nv_bfloat162*)lo)[i * 2]     = __halves2bfloat162(l[0], l[1]);
    ((__nv_bfloat162*)lo)[i * 2 + 1] = __halves2bfloat162(l[2], l[3]);
}

// Transpose + split: in [K][N] fp32 -> hi/lo [N][K] bf16 (for col-major mma B).
__global__ void transpose_split_kernel(const float* __restrict__ in,
                                       __nv_bfloat16* __restrict__ hi,
                                       __nv_bfloat16* __restrict__ lo, int K, int N) {
    __shared__ float tile[32][33];
    const int tx = threadIdx.x, ty = threadIdx.y;  // (32, 8)
    const int n0 = blockIdx.x * 32, k0 = blockIdx.y * 32;
#pragma unroll
    for (int j = 0; j < 4; j++)
        tile[ty + j * 8][tx] = in[(size_t)(k0 + ty + j * 8) * N + n0 + tx];
    __syncthreads();
#pragma unroll
    for (int j = 0; j < 4; j++) {
        float v = tile[tx][ty + j * 8];
        __nv_bfloat16 h, l;
        split_bf16(v, h, l);
        size_t o = (size_t)(n0 + ty + j * 8) * K + k0 + tx;
        hi[o] = h;
        lo[o] = l;
    }
}

// ---------------- bf16x3 tensor-core GEMM ----------------------------------------
// C[M,N] fp32 = A[M,K] @ B[K,N], A as hi/lo bf16 [M][K], B as hi/lo bf16
// TRANSPOSED [N][K]. mma.sync.m16n8k16.row.col, fp32 accum, 3 passes
// (AhBh + AhBl + AlBh). Block 128x128, 8 warps (4m x 2n), BK=16, double-buffered.
// Smem rows padded to 24 bf16 (48B = 12 banks): fragment loads conflict-free.
__device__ __forceinline__ void mma16816(float* c, const uint32_t* a,
                                         uint32_t b0, uint32_t b1) {
    asm volatile(
        "mma.sync.aligned.m16n8k16.row.col.f32.bf16.bf16.f32 "
        "{%0,%1,%2,%3}, {%4,%5,%6,%7}, {%8,%9}, {%0,%1,%2,%3};"
        : "+f"(c[0]), "+f"(c[1]), "+f"(c[2]), "+f"(c[3])
        : "r"(a[0]), "r"(a[1]), "r"(a[2]), "r"(a[3]), "r"(b0), "r"(b1));
}

__device__ __forceinline__ void mma_tile(const __nv_bfloat16* __restrict__ Ah,
                                         const __nv_bfloat16* __restrict__ Al,
                                         const __nv_bfloat16* __restrict__ Bh,
                                         const __nv_bfloat16* __restrict__ Bl,
                                         float* __restrict__ C,
                                         int N, int K, int row0, int col0) {
    __shared__ __nv_bfloat16 sA[2][2][128][24];  // [buf][hi/lo][m][k] pad 24
    __shared__ __nv_bfloat16 sB[2][2][128][24];  // [buf][hi/lo][n][k]
    const int tid = threadIdx.x;
    const int lane = tid & 31;
    const int wid = tid >> 5;
    const int wm = wid & 3;       // warp m: 4 x 32 rows
    const int wn = wid >> 2;      // warp n: 2 x 64 cols
    const int g = lane >> 2, q = lane & 3;
    const int srow = tid >> 1;          // 0..127
    const int sk = (tid & 1) * 8;       // 0 or 8

    const __nv_bfloat16* gAh = Ah + (size_t)(row0 + srow) * K + sk;
    const __nv_bfloat16* gAl = Al + (size_t)(row0 + srow) * K + sk;
    const __nv_bfloat16* gBh = Bh + (size_t)(col0 + srow) * K + sk;
    const __nv_bfloat16* gBl = Bl + (size_t)(col0 + srow) * K + sk;

    float acc[2][8][4];
#pragma unroll
    for (int mt = 0; mt < 2; mt++)
#pragma unroll
        for (int nt = 0; nt < 8; nt++)
#pragma unroll
            for (int e = 0; e < 4; e++) acc[mt][nt][e] = 0.f;

    // Preload k0 = 0 into buffer 0 (uint4 = 8 bf16 per array per thread).
    *(uint4*)&sA[0][0][srow][sk] = *(const uint4*)gAh;
    *(uint4*)&sA[0][1][srow][sk] = *(const uint4*)gAl;
    *(uint4*)&sB[0][0][srow][sk] = *(const uint4*)gBh;
    *(uint4*)&sB[0][1][srow][sk] = *(const uint4*)gBl;
    __syncthreads();

    int cur = 0;
    for (int k0 = 0; k0 < K; k0 += 16, cur ^= 1) {
        uint4 rAh, rAl, rBh, rBl;
        const bool more = (k0 + 16) < K;
        if (more) {
            rAh = *(const uint4*)(gAh + k0 + 16);
            rAl = *(const uint4*)(gAl + k0 + 16);
            rBh = *(const uint4*)(gBh + k0 + 16);
            rBl = *(const uint4*)(gBl + k0 + 16);
        }

        // A fragments for both 16-row tiles (hi and lo).
        uint32_t ah[2][4], al[2][4];
#pragma unroll
        for (int mt = 0; mt < 2; mt++) {
            const int mb = wm * 32 + mt * 16;
            ah[mt][0] = *(const uint32_t*)&sA[cur][0][mb + g][q * 2];
            ah[mt][1] = *(const uint32_t*)&sA[cur][0][mb + g + 8][q * 2];
            ah[mt][2] = *(const uint32_t*)&sA[cur][0][mb + g][q * 2 + 8];
            ah[mt][3] = *(const uint32_t*)&sA[cur][0][mb + g + 8][q * 2 + 8];
            al[mt][0] = *(const uint32_t*)&sA[cur][1][mb + g][q * 2];
            al[mt][1] = *(const uint32_t*)&sA[cur][1][mb + g + 8][q * 2];
            al[mt][2] = *(const uint32_t*)&sA[cur][1][mb + g][q * 2 + 8];
            al[mt][3] = *(const uint32_t*)&sA[cur][1][mb + g + 8][q * 2 + 8];
        }
#pragma unroll
        for (int nt = 0; nt < 8; nt++) {
            const int nb = wn * 64 + nt * 8;
            uint32_t bh0 = *(const uint32_t*)&sB[cur][0][nb + g][q * 2];
            uint32_t bh1 = *(const uint32_t*)&sB[cur][0][nb + g][q * 2 + 8];
            uint32_t bl0 = *(const uint32_t*)&sB[cur][1][nb + g][q * 2];
            uint32_t bl1 = *(const uint32_t*)&sB[cur][1][nb + g][q * 2 + 8];
#pragma unroll
            for (int mt = 0; mt < 2; mt++) {
                mma16816(acc[mt][nt], ah[mt], bh0, bh1);  // Ah*Bh
                mma16816(acc[mt][nt], ah[mt], bl0, bl1);  // Ah*Bl
                mma16816(acc[mt][nt], al[mt], bh0, bh1);  // Al*Bh
            }
        }

        if (more) {
            const int nxt = cur ^ 1;
            *(uint4*)&sA[nxt][0][srow][sk] = rAh;
            *(uint4*)&sA[nxt][1][srow][sk] = rAl;
            *(uint4*)&sB[nxt][0][srow][sk] = rBh;
            *(uint4*)&sB[nxt][1][srow][sk] = rBl;
        }
        __syncthreads();
    }

    // Epilogue: c0c1 -> (row, col..col+1), c2c3 -> (row+8, ...)
#pragma unroll
    for (int mt = 0; mt < 2; mt++) {
#pragma unroll
        for (int nt = 0; nt < 8; nt++) {
            const int row = row0 + wm * 32 + mt * 16 + g;
            const int col = col0 + wn * 64 + nt * 8 + q * 2;
            *(float2*)&C[(size_t)row * N + col] =
                make_float2(acc[mt][nt][0], acc[mt][nt][1]);
            *(float2*)&C[(size_t)(row + 8) * N + col] =
                make_float2(acc[mt][nt][2], acc[mt][nt][3]);
        }
    }
}

// Fused launch: QKV GEMM (by<32) and R GEMM (by>=32, bx<8) in one grid.
__global__ __launch_bounds__(256)
void qkv_rk_mma_kernel(const __nv_bfloat16* wh, const __nv_bfloat16* wl,
                       const __nv_bfloat16* qkth, const __nv_bfloat16* qktl,
                       float* qkv,
                       const __nv_bfloat16* rh, const __nv_bfloat16* rl,
                       const __nv_bfloat16* wrth, const __nv_bfloat16* wrtl,
                       float* rk) {
    if (blockIdx.y < 32) {
        mma_tile(wh, wl, qkth, qktl, qkv, QKVC, DM, blockIdx.y * 128, blockIdx.x * 128);
    } else if (blockIdx.x < 8) {
        mma_tile(rh, rl, wrth, wrtl, rk, DM, DM, (blockIdx.y - 32) * 128, blockIdx.x * 128);
    }
}

__global__ __launch_bounds__(256)
void wo_mma_kernel(const __nv_bfloat16* vh, const __nv_bfloat16* vl,
                   const __nv_bfloat16* woth, const __nv_bfloat16* wotl,
                   float* attn) {
    mma_tile(vh, vl, woth, wotl, attn, DM, DM, blockIdx.y * 128, blockIdx.x * 128);
}

// ---------------- fused flash attention with relative position -------------------
// (index math verified passing at rel_err 8.5e-8 in round 8; epilogue now emits
// the bf16 hi/lo split of vec directly for the Wo tensor-core GEMM)
#define SM_QW 0
#define SM_QR (64 * 68)
#define SM_U  (2 * 64 * 68)
#define SM_K  SM_U
#define SM_R  (SM_U + 64 * 68)
#define SM_P  SM_U
#define SM_V  (SM_U + 64 * 68)
#define SM_FLOATS (2 * 64 * 68 + 64 * 68 + 64 * 128)  // 21248 floats = 85 KB

__global__ __launch_bounds__(256, 2)
void flash_kernel(const float* __restrict__ qkv, const float* __restrict__ rk,
                  const float* __restrict__ rwb, const float* __restrict__ rrb,
                  __nv_bfloat16* __restrict__ vh, __nv_bfloat16* __restrict__ vl) {
    extern __shared__ float sm[];
    const int i0 = (15 - blockIdx.x) * 64;  // heavy tiles first
    const int bn = blockIdx.y;
    const int b = bn >> 4, n = bn & 15;
    const int tid = threadIdx.x;
    const int tx = tid & 15;   // d / jl micro (4 wide)
    const int ty = tid >> 4;   // il micro (4 wide)

    int vjl[4], vd[4];
#pragma unroll
    for (int k = 0; k < 4; k++) {
        int f = tid + k * 256;
        vjl[k] = f >> 4;
        vd[k] = (f & 15) * 4;
    }

    for (int t = tid; t < 64 * 64; t += 256) {
        int il = t >> 6, d = t & 63;
        float q = qkv[(size_t)((i0 + il) * 4 + b) * QKVC + n * 64 + d];
        sm[SM_QW + d * 68 + il] = q + rwb[n * 64 + d];
        sm[SM_QR + d * 68 + il] = q + rrb[n * 64 + d];
    }

    float acc[4][4];
    float m[4], l[4];
#pragma unroll
    for (int r = 0; r < 4; r++) {
        m[r] = -1e30f;
        l[r] = 0.f;
#pragma unroll
        for (int c = 0; c < 4; c++) acc[r][c] = 0.f;
    }

    const int ntiles = i0 / 64 + 1;
    const int pl0 = 60 - ty * 4 + tx * 4;

    for (int jt = 0; jt < ntiles; jt++) {
        const int j0 = jt * 64;

        float4 vreg[4];
#pragma unroll
        for (int k = 0; k < 4; k++) {
            vreg[k] = *(const float4*)&qkv[(size_t)((j0 + vjl[k]) * 4 + b) * QKVC +
                                           2048 + n * 64 + vd[k]];
        }

        __syncthreads();

        for (int t = tid; t < 64 * 64; t += 256) {
            int jl = t >> 6, d = t & 63;
            sm[SM_K + d * 68 + jl] =
                qkv[(size_t)((j0 + jl) * 4 + b) * QKVC + 1024 + n * 64 + d];
        }
        const int pbase = QL - 64 - i0 + j0;
        for (int t = tid; t < 64 * 128; t += 256) {
            int d = t >> 7, pl = t & 127;
            int p = pbase + pl;
            sm[SM_R + d * 128 + pl] = (p < QL) ? rk[(size_t)p * DM + n * 64 + d] : 0.f;
        }
        __syncthreads();

        float s[4][4];
#pragma unroll
        for (int r = 0; r < 4; r++)
#pragma unroll
            for (int c = 0; c < 4; c++) s[r][c] = 0.f;

#pragma unroll 4
        for (int d = 0; d < 64; d++) {
            float4 qw = *(const float4*)&sm[SM_QW + d * 68 + ty * 4];
            float4 qr = *(const float4*)&sm[SM_QR + d * 68 + ty * 4];
            float4 kk = *(const float4*)&sm[SM_K + d * 68 + tx * 4];
            float4 rA = *(const float4*)&sm[SM_R + d * 128 + pl0];
            float4 rB = *(const float4*)&sm[SM_R + d * 128 + pl0 + 4];
            float qwv[4] = {qw.x, qw.y, qw.z, qw.w};
            float qrv[4] = {qr.x, qr.y, qr.z, qr.w};
            float kv[4]  = {kk.x, kk.y, kk.z, kk.w};
            float rv[8]  = {rA.x, rA.y, rA.z, rA.w, rB.x, rB.y, rB.z, rB.w};
#pragma unroll
            for (int r = 0; r < 4; r++)
#pragma unroll
                for (int c = 0; c < 4; c++) {
                    s[r][c] += qwv[r] * kv[c];
                    s[r][c] += qrv[r] * rv[3 - r + c];
                }
        }

#pragma unroll
        for (int r = 0; r < 4; r++) {
            int i = i0 + ty * 4 + r;
#pragma unroll
            for (int c = 0; c < 4; c++) {
                int j = j0 + tx * 4 + c;
                s[r][c] = (j <= i) ? s[r][c] * 0.125f : -1e30f;
            }
        }

        float rowsum[4];
#pragma unroll
        for (int r = 0; r < 4; r++) {
            float mx = fmaxf(fmaxf(s[r][0], s[r][1]), fmaxf(s[r][2], s[r][3]));
#pragma unroll
            for (int o = 1; o < 16; o <<= 1)
                mx = fmaxf(mx, __shfl_xor_sync(0xffffffffu, mx, o));
            float mnew = fmaxf(m[r], mx);
            float sc = __expf(m[r] - mnew);
            m[r] = mnew;
            l[r] *= sc;
#pragma unroll
            for (int c = 0; c < 4; c++) acc[r][c] *= sc;
            float rs = 0.f;
#pragma unroll
            for (int c = 0; c < 4; c++) {
                float p = __expf(s[r][c] - mnew);
                s[r][c] = p;
                rs += p;
            }
            rowsum[r] = rs;
        }
#pragma unroll
        for (int r = 0; r < 4; r++) {
#pragma unroll
            for (int o = 1; o < 16; o <<= 1)
                rowsum[r] += __shfl_xor_sync(0xffffffffu, rowsum[r], o);
            l[r] += rowsum[r];
        }

        __syncthreads();

#pragma unroll
        for (int r = 0; r < 4; r++) {
            float4 pv = make_float4(s[r][0], s[r][1], s[r][2], s[r][3]);
            *(float4*)&sm[SM_P + (ty * 4 + r) * 68 + tx * 4] = pv;
        }
#pragma unroll
        for (int k = 0; k < 4; k++) {
            *(float4*)&sm[SM_V + vjl[k] * 68 + vd[k]] = vreg[k];
        }
        __syncthreads();

#pragma unroll 4
        for (int jl = 0; jl < 64; jl++) {
            float pr[4];
#pragma unroll
            for (int r = 0; r < 4; r++) pr[r] = sm[SM_P + (ty * 4 + r) * 68 + jl];
            float4 vv = *(const float4*)&sm[SM_V + jl * 68 + tx * 4];
            float vvv[4] = {vv.x, vv.y, vv.z, vv.w};
#pragma unroll
            for (int r = 0; r < 4; r++)
#pragma unroll
                for (int c = 0; c < 4; c++) acc[r][c] += pr[r] * vvv[c];
        }
    }

    // ---- epilogue: normalize and write bf16 hi/lo split of vec directly ----
#pragma unroll
    for (int r = 0; r < 4; r++) {
        float inv = 1.f / l[r];
        int i = i0 + ty * 4 + r;
        size_t o = ((size_t)(i * 4 + b) * DM + n * 64 + tx * 4) >> 1;  // bf162 index
        __nv_bfloat16 h[4], lo[4];
#pragma unroll
        for (int c = 0; c < 4; c++) split_bf16(acc[r][c] * inv, h[c], lo[c]);
        ((__nv_bfloat162*)vh)[o]     = __halves2bfloat162(h[0], h[1]);
        ((__nv_bfloat162*)vh)[o + 1] = __halves2bfloat162(h[2], h[3]);
        ((__nv_bfloat162*)vl)[o]     = __halves2bfloat162(lo[0], lo[1]);
        ((__nv_bfloat162*)vl)[o + 1] = __halves2bfloat162(lo[2], lo[3]);
    }
}

// ---------------- residual + LayerNorm (float4 + warp-shuffle reduction) ---------
__global__ void ln_kernel(const float* __restrict__ w, const float* __restrict__ attn,
                          const float* __restrict__ gamma, const float* __restrict__ beta,
                          float* __restrict__ out) {
    const int row = blockIdx.x;
    const int tid = threadIdx.x;  // 256 threads, 1 float4 each
    __shared__ float warp_s[8], warp_s2[8], stats[2];

    const float4 wv = *(const float4*)(w + (size_t)row * DM + tid * 4);
    const float4 av = *(const float4*)(attn + (size_t)row * DM + tid * 4);
    float4 v = make_float4(wv.x + av.x, wv.y + av.y, wv.z + av.z, wv.w + av.w);

    float s = v.x + v.y + v.z + v.w;
    float s2 = v.x * v.x + v.y * v.y + v.z * v.z + v.w * v.w;
#pragma unroll
    for (int o = 16; o > 0; o >>= 1) {
        s += __shfl_xor_sync(0xffffffffu, s, o);
        s2 += __shfl_xor_sync(0xffffffffu, s2, o);
    }
    if ((tid & 31) == 0) {
        warp_s[tid >> 5] = s;
        warp_s2[tid >> 5] = s2;
    }
    __syncthreads();
    if (tid < 32) {
        float ps = (tid < 8) ? warp_s[tid] : 0.f;
        float ps2 = (tid < 8) ? warp_s2[tid] : 0.f;
#pragma unroll
        for (int o = 4; o > 0; o >>= 1) {
            ps += __shfl_xor_sync(0xffffffffu, ps, o);
            ps2 += __shfl_xor_sync(0xffffffffu, ps2, o);
        }
        if (tid == 0) {
            float mu = ps * (1.f / DM);
            float var = ps2 * (1.f / DM) - mu * mu;
            stats[0] = mu;
            stats[1] = rsqrtf(var + 1e-5f);
        }
    }
    __syncthreads();
    const float mu = stats[0], rstd = stats[1];
    const float4 g4 = *(const float4*)(gamma + tid * 4);
    const float4 b4 = *(const float4*)(beta + tid * 4);
    float4 o4;
    o4.x = (v.x - mu) * rstd * g4.x + b4.x;
    o4.y = (v.y - mu) * rstd * g4.y + b4.y;
    o4.z = (v.z - mu) * rstd * g4.z + b4.z;
    o4.w = (v.w - mu) * rstd * g4.w + b4.w;
    *(float4*)(out + (size_t)row * DM + tid * 4) = o4;
}

// ---------------- launch ---------------------------------------------------------
extern "C" void kernel_launch(void* const* d_in, const int* in_sizes, int n_in,
                              void* d_out, int out_size) {
    const float* w    = (const float*)d_in[0];  // [1024, 4, 1024]
    const float* r    = (const float*)d_in[1];  // [1024, 1024]
    const float* rwb  = (const float*)d_in[2];  // [16, 64]
    const float* rrb  = (const float*)d_in[3];  // [16, 64]
    // d_in[4] = attn_mask (fixed causal tril) -- computed analytically
    const float* Wqkv = (const float*)d_in[5];  // [1024, 3072]
    const float* Wr   = (const float*)d_in[6];  // [1024, 1024]
    const float* Wo   = (const float*)d_in[7];  // [1024, 1024]
    const float* gam  = (const float*)d_in[8];  // [1024]
    const float* bet  = (const float*)d_in[9];  // [1024]
    float* out = (float*)d_out;

    float *qkv, *rk, *attn;
    cudaGetSymbolAddress((void**)&qkv, g_qkv);
    cudaGetSymbolAddress((void**)&rk, g_rk);
    cudaGetSymbolAddress((void**)&attn, g_attn);

    __nv_bfloat16 *wh, *wl, *rh, *rl, *vh, *vl, *qkth, *qktl, *wrth, *wrtl, *woth, *wotl;
    cudaGetSymbolAddress((void**)&wh, g_wh);
    cudaGetSymbolAddress((void**)&wl, g_wl);
    cudaGetSymbolAddress((void**)&rh, g_rh);
    cudaGetSymbolAddress((void**)&rl, g_rl);
    cudaGetSymbolAddress((void**)&vh, g_vh);
    cudaGetSymbolAddress((void**)&vl, g_vl);
    cudaGetSymbolAddress((void**)&qkth, g_qkt_h);
    cudaGetSymbolAddress((void**)&qktl, g_qkt_l);
    cudaGetSymbolAddress((void**)&wrth, g_wrt_h);
    cudaGetSymbolAddress((void**)&wrtl, g_wrt_l);
    cudaGetSymbolAddress((void**)&woth, g_wot_h);
    cudaGetSymbolAddress((void**)&wotl, g_wot_l);

    cudaFuncSetAttribute(flash_kernel, cudaFuncAttributeMaxDynamicSharedMemorySize,
                         SM_FLOATS * sizeof(float));

    // 0) split inputs to bf16 hi/lo (A-side) and split+transpose weights (B-side)
    convert_split_kernel<<<(ROWS * DM / 4) / 256, 256>>>(w, wh, wl, ROWS * DM / 4);
    convert_split_kernel<<<(QL * DM / 4) / 256, 256>>>(r, rh, rl, QL * DM / 4);
    transpose_split_kernel<<<dim3(QKVC / 32, DM / 32), dim3(32, 8)>>>(Wqkv, qkth, qktl, DM, QKVC);
    transpose_split_kernel<<<dim3(DM / 32, DM / 32), dim3(32, 8)>>>(Wr, wrth, wrtl, DM, DM);
    transpose_split_kernel<<<dim3(DM / 32, DM / 32), dim3(32, 8)>>>(Wo, woth, wotl, DM, DM);

    // 1+2) heads = w @ W_qkv fused with r_k = r @ W_r (tensor-core bf16x3)
    qkv_rk_mma_kernel<<<dim3(24, 40), 256>>>(wh, wl, qkth, qktl, qkv,
                                             rh, rl, wrth, wrtl, rk);
    // 3) fused attention; epilogue emits bf16 hi/lo vec directly
    flash_kernel<<<dim3(16, 64), 256, SM_FLOATS * sizeof(float)>>>(qkv, rk, rwb, rrb, vh, vl);
    // 4) attn_out = vec @ W_o (tensor-core bf16x3)
    wo_mma_kernel<<<dim3(8, 32), 256>>>(vh, vl, woth, wotl, attn);
    // 5) layer_norm(w + attn_out)
    ln_kernel<<<ROWS, 256>>>(w, attn, gam, bet, out);
}